// round 5
// baseline (speedup 1.0000x reference)
#include <cuda_runtime.h>
#include <math.h>

// ----------------------------------------------------------------------------
// UVMD block: modes_k = irfft( c_k(f) * rfft(x_row) )
// The per-frequency Jacobi recurrence is linear in f_hat with real
// coefficients, so it collapses to one real filter gain c_k(f) per mode,
// computed once in the init kernel.
// ----------------------------------------------------------------------------

#define TLEN 4096
#define MLEN 2048
#define NF   2049
#define KM   8
#define LI   8
#define CCH  16

#define WBUF 2304                 // 2048 + 2048/8 padding
#define XBUF 2056
#define SMEM_FLOATS (4*WBUF + 2*XBUF)
#define SMEM_BYTES  (SMEM_FLOATS * 4)

__device__ float2 d_twN[4096];        // e^{-2*pi*i*j/4096}
__device__ float  d_cc[KM][NF];       // c_k(f) / 2048  (irfft scale folded in)

// ------------------------------ init kernel --------------------------------
__global__ void uvmd_init(const float* __restrict__ log_alpha,
                          const float* __restrict__ raw_tau,
                          const float* __restrict__ raw_omega) {
    int j = blockIdx.x * blockDim.x + threadIdx.x;
    if (j < 4096) {
        double ang = -2.0 * 3.14159265358979323846 * (double)j / 4096.0;
        d_twN[j] = make_float2((float)cos(ang), (float)sin(ang));
    }
    if (j < NF) {
        double freq = (double)j / 4096.0;   // linspace(0, 0.5, 2049)
        double omega[KM];
        #pragma unroll
        for (int k = 0; k < KM; k++) {
            double s = 1.0 / (1.0 + exp(-(double)raw_omega[k]));
            omega[k] = 0.5 * s;
        }
        double c[KM];
        double g = 0.0;
        #pragma unroll
        for (int k = 0; k < KM; k++) c[k] = 0.0;
        for (int l = 0; l < LI; l++) {
            double tau = log1p(exp((double)raw_tau[l]));   // softplus
            double S = 0.0;
            #pragma unroll
            for (int k = 0; k < KM; k++) S += c[k];
            double cn[KM];
            double Sn = 0.0;
            #pragma unroll
            for (int k = 0; k < KM; k++) {
                double alpha = exp((double)log_alpha[l*KM + k]);
                double df = freq - omega[k];
                double den = 1.0 + 2.0 * alpha * df * df;
                cn[k] = (1.0 - (S - c[k]) + 0.5 * g) / den;
                Sn += cn[k];
            }
            g += tau * (1.0 - Sn);
            #pragma unroll
            for (int k = 0; k < KM; k++) c[k] = cn[k];
        }
        #pragma unroll
        for (int k = 0; k < KM; k++)
            d_cc[k][j] = (float)(c[k] * (1.0 / 2048.0));
    }
}

// ------------------------------ FFT helpers --------------------------------
__device__ __forceinline__ float2 cmulf2(float2 a, float2 b) {
    return make_float2(a.x*b.x - a.y*b.y, a.x*b.y + a.y*b.x);
}
template<bool INV>
__device__ __forceinline__ float2 twmul(float2 a, float2 w) {
    // table holds e^{-i*theta}; inverse uses conj
    float wy = INV ? -w.y : w.y;
    return make_float2(a.x*w.x - a.y*wy, a.x*wy + a.y*w.x);
}
template<bool INV>
__device__ __forceinline__ float2 rot90(float2 z) {
    // forward: -i*z ; inverse: +i*z
    return INV ? make_float2(-z.y, z.x) : make_float2(z.y, -z.x);
}
template<bool INV>
__device__ __forceinline__ void dft4(float2 u0, float2 u1, float2 u2, float2 u3,
                                     float2* e) {
    float2 s0 = make_float2(u0.x + u2.x, u0.y + u2.y);
    float2 d0 = make_float2(u0.x - u2.x, u0.y - u2.y);
    float2 s1 = make_float2(u1.x + u3.x, u1.y + u3.y);
    float2 d1 = make_float2(u1.x - u3.x, u1.y - u3.y);
    float2 r1 = rot90<INV>(d1);
    e[0] = make_float2(s0.x + s1.x, s0.y + s1.y);
    e[1] = make_float2(d0.x + r1.x, d0.y + r1.y);
    e[2] = make_float2(s0.x - s1.x, s0.y - s1.y);
    e[3] = make_float2(d0.x - r1.x, d0.y - r1.y);
}

// Stockham DIF radix-8 stage: (n, s) -> (n/8, 8s). (n/8)*s == 256 butterflies.
template<bool INV, int N, int S>
__device__ __forceinline__ void stage_r8(const float* __restrict__ xr,
                                         const float* __restrict__ xi,
                                         float* __restrict__ yr,
                                         float* __restrict__ yi, int tid) {
    constexpr int ND8  = N / 8;
    constexpr int STEP = 4096 / N;
    int p = tid / S;
    int q = tid - p * S;
    float2 v[8];
    #pragma unroll
    for (int t = 0; t < 8; t++) {
        int idx = q + S * (p + t * ND8);
        int pi = idx + (idx >> 3);
        v[t] = make_float2(xr[pi], xi[pi]);
    }
    float2 E[4], O[4];
    dft4<INV>(v[0], v[2], v[4], v[6], E);
    dft4<INV>(v[1], v[3], v[5], v[7], O);
    const float RS = 0.7071067811865476f;
    O[1] = cmulf2(O[1], make_float2( RS, INV ?  RS : -RS));
    O[2] = rot90<INV>(O[2]);
    O[3] = cmulf2(O[3], make_float2(-RS, INV ?  RS : -RS));
    float2 y[8];
    #pragma unroll
    for (int r = 0; r < 4; r++) {
        y[r]   = make_float2(E[r].x + O[r].x, E[r].y + O[r].y);
        y[r+4] = make_float2(E[r].x - O[r].x, E[r].y - O[r].y);
    }
    #pragma unroll
    for (int r = 0; r < 8; r++) {
        float2 t = y[r];
        if (r) t = twmul<INV>(t, d_twN[(p * r * STEP) & 4095]);
        int idx = q + S * (8 * p + r);
        int pi = idx + (idx >> 3);
        yr[pi] = t.x; yi[pi] = t.y;
    }
}

// Final Stockham radix-4 stage: (4, 512) -> done. Twiddle-free (p==0).
template<bool INV>
__device__ __forceinline__ void stage_r4(const float* __restrict__ xr,
                                         const float* __restrict__ xi,
                                         float* __restrict__ yr,
                                         float* __restrict__ yi, int tid) {
    #pragma unroll
    for (int it = 0; it < 2; it++) {
        int q = tid + it * 256;
        float2 v[4];
        #pragma unroll
        for (int t = 0; t < 4; t++) {
            int idx = q + 512 * t;
            int pi = idx + (idx >> 3);
            v[t] = make_float2(xr[pi], xi[pi]);
        }
        float2 e[4];
        dft4<INV>(v[0], v[1], v[2], v[3], e);
        #pragma unroll
        for (int r = 0; r < 4; r++) {
            int idx = q + 512 * r;
            int pi = idx + (idx >> 3);
            yr[pi] = e[r].x; yi[pi] = e[r].y;
        }
    }
}

// 2048-pt complex FFT, natural order in/out, input in A, output in A.
template<bool INV>
__device__ __forceinline__ void fft2048(float* Ar, float* Ai, float* Br, float* Bi,
                                        int tid) {
    stage_r8<INV, 2048, 1 >(Ar, Ai, Br, Bi, tid); __syncthreads();
    stage_r8<INV,  256, 8 >(Br, Bi, Ar, Ai, tid); __syncthreads();
    stage_r8<INV,   32, 64>(Ar, Ai, Br, Bi, tid); __syncthreads();
    stage_r4<INV>(Br, Bi, Ar, Ai, tid);           __syncthreads();
}

// ------------------------------ main kernel --------------------------------
__global__ void __launch_bounds__(256)
uvmd_main(const float* __restrict__ x, float* __restrict__ out) {
    int r = blockIdx.x;
    int b = r >> 4;
    int c = r & 15;
    int tid = threadIdx.x;

    extern __shared__ float sm[];
    float* Ar = sm;
    float* Ai = Ar + WBUF;
    float* Br = Ai + WBUF;
    float* Bi = Br + WBUF;
    float* Xr = Bi + WBUF;
    float* Xi = Xr + XBUF;

    const float* xrow = x + (size_t)b * TLEN * CCH + c;

    // Pack: z[n] = x[2n] + i*x[2n+1]
    #pragma unroll
    for (int j = 0; j < 8; j++) {
        int n  = tid + j * 256;
        int pi = n + (n >> 3);
        Ar[pi] = xrow[(2 * n)     * CCH];
        Ai[pi] = xrow[(2 * n + 1) * CCH];
    }
    __syncthreads();

    // Forward complex FFT
    fft2048<false>(Ar, Ai, Br, Bi, tid);

    // Untangle -> X[0..2048] (rfft of the real row)
    for (int f = tid; f <= 1024; f += 256) {
        int fm  = (2048 - f) & 2047;
        int pf  = f  + (f  >> 3);
        int pfm = fm + (fm >> 3);
        float2 Zf = make_float2(Ar[pf],  Ai[pf]);
        float2 Zm = make_float2(Ar[pfm], Ai[pfm]);
        float2 E = make_float2(0.5f * (Zf.x + Zm.x), 0.5f * (Zf.y - Zm.y));
        float2 D = make_float2(0.5f * (Zf.x - Zm.x), 0.5f * (Zf.y + Zm.y));
        float2 W = d_twN[f];                 // e^{-2*pi*i*f/4096}
        float2 V = cmulf2(D, W);
        // X[f] = E - i*V ; X[2048-f] = conj(E + i*V)
        Xr[f] = E.x + V.y;        Xi[f] = E.y - V.x;
        Xr[2048 - f] = E.x - V.y; Xi[2048 - f] = -(E.y + V.x);
    }
    __syncthreads();

    // Per-mode: filter + inverse real FFT + strided store
    for (int k = 0; k < KM; k++) {
        for (int f = tid; f <= 1024; f += 256) {
            float cf = d_cc[k][f];
            float cm = d_cc[k][2048 - f];
            float2 Yf = make_float2(cf * Xr[f],        cf * Xi[f]);
            float2 Ym = make_float2(cm * Xr[2048 - f], cm * Xi[2048 - f]);
            float2 E = make_float2(0.5f * (Yf.x + Ym.x), 0.5f * (Yf.y - Ym.y));
            float2 G = make_float2(0.5f * (Yf.x - Ym.x), 0.5f * (Yf.y + Ym.y));
            float2 W = d_twN[f];
            // O = G * conj(W)
            float2 O = make_float2(G.x * W.x + G.y * W.y, G.y * W.x - G.x * W.y);
            // Z[f] = E + i*O
            int pf = f + (f >> 3);
            Ar[pf] = E.x - O.y;
            Ai[pf] = E.y + O.x;
            if (f != 0 && f != 1024) {
                // Z[2048-f] = conj(E - i*O)
                int fm = 2048 - f;
                int pm = fm + (fm >> 3);
                Ar[pm] = E.x + O.y;
                Ai[pm] = O.x - E.y;
            }
        }
        __syncthreads();

        fft2048<true>(Ar, Ai, Br, Bi, tid);

        // out[b, k, t, c]: even t = Re z, odd t = Im z
        float* orow = out + ((size_t)(b * KM + k) * TLEN) * CCH + c;
        #pragma unroll
        for (int j = 0; j < 8; j++) {
            int n  = tid + j * 256;
            int pi = n + (n >> 3);
            orow[(2 * n)     * CCH] = Ar[pi];
            orow[(2 * n + 1) * CCH] = Ai[pi];
        }
        __syncthreads();   // A reused next k
    }
}

// ------------------------------ launch -------------------------------------
extern "C" void kernel_launch(void* const* d_in, const int* in_sizes, int n_in,
                              void* d_out, int out_size) {
    const float* x  = (const float*)d_in[0];
    const float* la = (const float*)d_in[1];
    const float* rt = (const float*)d_in[2];
    const float* rw = (const float*)d_in[3];
    float* out = (float*)d_out;

    cudaFuncSetAttribute(uvmd_main, cudaFuncAttributeMaxDynamicSharedMemorySize,
                         SMEM_BYTES);

    uvmd_init<<<16, 256>>>(la, rt, rw);
    uvmd_main<<<1024, 256, SMEM_BYTES>>>(x, out);
}

// round 7
// speedup vs baseline: 1.3215x; 1.3215x over previous
#include <cuda_runtime.h>
#include <math.h>

// ----------------------------------------------------------------------------
// UVMD block: modes_k = irfft( c_k(f) * rfft(x_row) )
// c_k(f) is real; extended evenly to the full 4096-bin spectrum it is a real
// even filter, so it acts independently on Re/Im of a complex signal. We pair
// adjacent channels:  Z = fft4096(x_c + i x_{c+1});  z_k = ifft4096(ck .* Z);
// Re z_k -> mode_k[ch c], Im z_k -> mode_k[ch c+1].  No pack/untangle passes,
// and global I/O becomes float2 (adjacent channels are adjacent in memory).
// ----------------------------------------------------------------------------

#define TLEN 4096
#define NF   2049
#define KM   8
#define LI   8
#define CCH  16
#define NTH  512

#define WBUF 4608                 // 4096 + 4096/8 padding
#define SMEM_FLOATS (6 * WBUF)
#define SMEM_BYTES  (SMEM_FLOATS * 4)   // 110592 B -> 2 CTAs/SM

__device__ float2 d_twN[4096];          // e^{-2*pi*i*j/4096}
__device__ float  d_ccx[KM][4096];      // even-extended c_k(f) / 4096

// ------------------------------ init kernel --------------------------------
__global__ void uvmd_init(const float* __restrict__ log_alpha,
                          const float* __restrict__ raw_tau,
                          const float* __restrict__ raw_omega) {
    int j = blockIdx.x * blockDim.x + threadIdx.x;
    if (j >= 4096) return;

    double ang = -2.0 * 3.14159265358979323846 * (double)j / 4096.0;
    d_twN[j] = make_float2((float)cos(ang), (float)sin(ang));

    int m = (j <= 2048) ? j : (4096 - j);        // even extension
    double freq = (double)m / 4096.0;            // linspace(0,0.5,2049)

    double omega[KM];
    #pragma unroll
    for (int k = 0; k < KM; k++) {
        double s = 1.0 / (1.0 + exp(-(double)raw_omega[k]));
        omega[k] = 0.5 * s;
    }
    double c[KM];
    double g = 0.0;
    #pragma unroll
    for (int k = 0; k < KM; k++) c[k] = 0.0;
    for (int l = 0; l < LI; l++) {
        double tau = log1p(exp((double)raw_tau[l]));   // softplus
        double S = 0.0;
        #pragma unroll
        for (int k = 0; k < KM; k++) S += c[k];
        double cn[KM];
        double Sn = 0.0;
        #pragma unroll
        for (int k = 0; k < KM; k++) {
            double alpha = exp((double)log_alpha[l*KM + k]);
            double df = freq - omega[k];
            double den = 1.0 + 2.0 * alpha * df * df;
            cn[k] = (1.0 - (S - c[k]) + 0.5 * g) / den;
            Sn += cn[k];
        }
        g += tau * (1.0 - Sn);
        #pragma unroll
        for (int k = 0; k < KM; k++) c[k] = cn[k];
    }
    #pragma unroll
    for (int k = 0; k < KM; k++)
        d_ccx[k][j] = (float)(c[k] * (1.0 / 4096.0));  // ifft scale folded in
}

// ------------------------------ FFT helpers --------------------------------
__device__ __forceinline__ float2 cmulf2(float2 a, float2 b) {
    return make_float2(a.x*b.x - a.y*b.y, a.x*b.y + a.y*b.x);
}
template<bool INV>
__device__ __forceinline__ float2 twmul(float2 a, float2 w) {
    // table holds e^{-i*theta}; inverse uses conj
    float wy = INV ? -w.y : w.y;
    return make_float2(a.x*w.x - a.y*wy, a.x*wy + a.y*w.x);
}
template<bool INV>
__device__ __forceinline__ float2 rot90(float2 z) {
    // forward: -i*z ; inverse: +i*z
    return INV ? make_float2(-z.y, z.x) : make_float2(z.y, -z.x);
}
template<bool INV>
__device__ __forceinline__ void dft4(float2 u0, float2 u1, float2 u2, float2 u3,
                                     float2* e) {
    float2 s0 = make_float2(u0.x + u2.x, u0.y + u2.y);
    float2 d0 = make_float2(u0.x - u2.x, u0.y - u2.y);
    float2 s1 = make_float2(u1.x + u3.x, u1.y + u3.y);
    float2 d1 = make_float2(u1.x - u3.x, u1.y - u3.y);
    float2 r1 = rot90<INV>(d1);
    e[0] = make_float2(s0.x + s1.x, s0.y + s1.y);
    e[1] = make_float2(d0.x + r1.x, d0.y + r1.y);
    e[2] = make_float2(s0.x - s1.x, s0.y - s1.y);
    e[3] = make_float2(d0.x - r1.x, d0.y - r1.y);
}

template<bool INV>
__device__ __forceinline__ void bfly8(float2* v, float2* y) {
    float2 E[4], O[4];
    dft4<INV>(v[0], v[2], v[4], v[6], E);
    dft4<INV>(v[1], v[3], v[5], v[7], O);
    const float RS = 0.7071067811865476f;
    O[1] = cmulf2(O[1], make_float2( RS, INV ?  RS : -RS));
    O[2] = rot90<INV>(O[2]);
    O[3] = cmulf2(O[3], make_float2(-RS, INV ?  RS : -RS));
    #pragma unroll
    for (int r = 0; r < 4; r++) {
        y[r]   = make_float2(E[r].x + O[r].x, E[r].y + O[r].y);
        y[r+4] = make_float2(E[r].x - O[r].x, E[r].y - O[r].y);
    }
}

// Stockham DIF radix-8 stage over 4096 points, 512 threads, 1 butterfly each.
// Reads at logical idx = tid + 512*t (always conflict-free after padding).
template<bool INV, int N, int S>
__device__ __forceinline__ void stage_r8(const float* __restrict__ xr,
                                         const float* __restrict__ xi,
                                         float* __restrict__ yr,
                                         float* __restrict__ yi, int tid) {
    constexpr int STEP = 4096 / N;
    int p = tid / S;
    int q = tid - p * S;
    float2 v[8];
    #pragma unroll
    for (int t = 0; t < 8; t++) {
        int idx = tid + 512 * t;
        int pi = idx + (idx >> 3);
        v[t] = make_float2(xr[pi], xi[pi]);
    }
    float2 y[8];
    bfly8<INV>(v, y);
    #pragma unroll
    for (int r = 0; r < 8; r++) {
        float2 t2 = y[r];
        if (r) t2 = twmul<INV>(t2, d_twN[(p * r * STEP) & 4095]);
        int idx = q + S * (8 * p + r);
        int pi = idx + (idx >> 3);
        yr[pi] = t2.x; yi[pi] = t2.y;
    }
}

// First inverse stage with the real filter fused into the load (N=4096, S=1).
__device__ __forceinline__ void stage_r8_filt(const float* __restrict__ xr,
                                              const float* __restrict__ xi,
                                              float* __restrict__ yr,
                                              float* __restrict__ yi,
                                              const float* __restrict__ cc,
                                              int tid) {
    int p = tid;
    float2 v[8];
    #pragma unroll
    for (int t = 0; t < 8; t++) {
        int idx = tid + 512 * t;
        int pi = idx + (idx >> 3);
        float cf = cc[idx];
        v[t] = make_float2(cf * xr[pi], cf * xi[pi]);
    }
    float2 y[8];
    bfly8<true>(v, y);
    #pragma unroll
    for (int r = 0; r < 8; r++) {
        float2 t2 = y[r];
        if (r) t2 = twmul<true>(t2, d_twN[(p * r) & 4095]);
        int idx = 8 * p + r;
        int pi = idx + (idx >> 3);
        yr[pi] = t2.x; yi[pi] = t2.y;
    }
}

// ------------------------------ main kernel --------------------------------
__global__ void __launch_bounds__(NTH, 2)
uvmd_main(const float* __restrict__ x, float* __restrict__ out) {
    int pr = blockIdx.x;
    int b  = pr >> 3;            // batch
    int c  = (pr & 7) << 1;      // even channel of the pair
    int tid = threadIdx.x;

    extern __shared__ float sm[];
    float* Zr = sm;
    float* Zi = Zr + WBUF;
    float* Br = Zi + WBUF;
    float* Bi = Br + WBUF;
    float* Cr = Bi + WBUF;
    float* Ci = Cr + WBUF;

    // Load pair: z[t] = x[b,t,c] + i*x[b,t,c+1]   (float2, stride 64B)
    const float2* xrow = (const float2*)(x + (size_t)b * TLEN * CCH + c);
    #pragma unroll
    for (int j = 0; j < 8; j++) {
        int n  = tid + j * NTH;
        int pi = n + (n >> 3);
        float2 v = xrow[n * (CCH / 2)];
        Br[pi] = v.x; Bi[pi] = v.y;
    }
    __syncthreads();

    // Forward 4096-pt complex FFT: B -> C -> B -> C -> Z
    stage_r8<false, 4096,   1>(Br, Bi, Cr, Ci, tid); __syncthreads();
    stage_r8<false,  512,   8>(Cr, Ci, Br, Bi, tid); __syncthreads();
    stage_r8<false,   64,  64>(Br, Bi, Cr, Ci, tid); __syncthreads();
    stage_r8<false,    8, 512>(Cr, Ci, Zr, Zi, tid); __syncthreads();

    // Per-mode: (filter ⊙ Z) -> ifft -> float2 store
    #pragma unroll 1
    for (int k = 0; k < KM; k++) {
        stage_r8_filt(Zr, Zi, Br, Bi, d_ccx[k], tid);  __syncthreads();
        stage_r8<true,  512,   8>(Br, Bi, Cr, Ci, tid); __syncthreads();
        stage_r8<true,   64,  64>(Cr, Ci, Br, Bi, tid); __syncthreads();
        stage_r8<true,    8, 512>(Br, Bi, Cr, Ci, tid); __syncthreads();

        // out[b,k,t,c] = Re, out[b,k,t,c+1] = Im  (float2, stride 64B)
        float2* orow = (float2*)(out + ((size_t)(b * KM + k) * TLEN) * CCH + c);
        #pragma unroll
        for (int j = 0; j < 8; j++) {
            int n  = tid + j * NTH;
            int pi = n + (n >> 3);
            orow[n * (CCH / 2)] = make_float2(Cr[pi], Ci[pi]);
        }
        // No extra sync needed: the sync after next k's stage_r8_filt orders
        // these C reads before stage 2 overwrites C.
    }
}

// ------------------------------ launch -------------------------------------
extern "C" void kernel_launch(void* const* d_in, const int* in_sizes, int n_in,
                              void* d_out, int out_size) {
    const float* x  = (const float*)d_in[0];
    const float* la = (const float*)d_in[1];
    const float* rt = (const float*)d_in[2];
    const float* rw = (const float*)d_in[3];
    float* out = (float*)d_out;

    cudaFuncSetAttribute(uvmd_main, cudaFuncAttributeMaxDynamicSharedMemorySize,
                         SMEM_BYTES);

    uvmd_init<<<16, 256>>>(la, rt, rw);
    uvmd_main<<<64 * 8, NTH, SMEM_BYTES>>>(x, out);
}

// round 8
// speedup vs baseline: 3.3440x; 2.5304x over previous
#include <cuda_runtime.h>
#include <math.h>

// ----------------------------------------------------------------------------
// UVMD block: modes_k = irfft( c_k(f) * rfft(x_row) )
// c_k(f) is real and even-extended over the 4096-bin spectrum, so it acts
// independently on Re/Im of a complex signal. Pair adjacent channels:
//   Z = fft4096(x_c + i x_{c+1});  z_k = ifft4096(ck .* Z)
//   Re z_k -> mode_k[ch c], Im z_k -> mode_k[ch c+1]
// R8: fp32 init (fp64 init was ~190us!), stage-1 fused with global load,
// stage-4 fused with global store (twiddle-free), twiddles computed on the
// fly (sincospif + power chain) instead of table loads.
// ----------------------------------------------------------------------------

#define TLEN 4096
#define KM   8
#define LI   8
#define CCH  16
#define NTH  512

#define WBUF 4608                 // 4096 + 4096/8 padding
#define SMEM_FLOATS (6 * WBUF)
#define SMEM_BYTES  (SMEM_FLOATS * 4)   // 110592 B -> 2 CTAs/SM

__device__ float d_ccx[KM][4096];       // even-extended c_k(f) / 4096

// ------------------------------ init kernel --------------------------------
__global__ void uvmd_init(const float* __restrict__ log_alpha,
                          const float* __restrict__ raw_tau,
                          const float* __restrict__ raw_omega) {
    int j = blockIdx.x * blockDim.x + threadIdx.x;
    if (j >= 4096) return;

    int m = (j <= 2048) ? j : (4096 - j);        // even extension
    float freq = (float)m * (1.0f / 4096.0f);    // linspace(0,0.5,2049)

    float omega[KM];
    #pragma unroll
    for (int k = 0; k < KM; k++)
        omega[k] = 0.5f / (1.0f + expf(-raw_omega[k]));

    float c[KM];
    float g = 0.0f;
    #pragma unroll
    for (int k = 0; k < KM; k++) c[k] = 0.0f;
    for (int l = 0; l < LI; l++) {
        float tau = log1pf(expf(raw_tau[l]));    // softplus
        float S = 0.0f;
        #pragma unroll
        for (int k = 0; k < KM; k++) S += c[k];
        float cn[KM];
        float Sn = 0.0f;
        #pragma unroll
        for (int k = 0; k < KM; k++) {
            float alpha = expf(log_alpha[l*KM + k]);
            float df = freq - omega[k];
            float den = 1.0f + 2.0f * alpha * df * df;
            cn[k] = (1.0f - (S - c[k]) + 0.5f * g) / den;
            Sn += cn[k];
        }
        g += tau * (1.0f - Sn);
        #pragma unroll
        for (int k = 0; k < KM; k++) c[k] = cn[k];
    }
    #pragma unroll
    for (int k = 0; k < KM; k++)
        d_ccx[k][j] = c[k] * (1.0f / 4096.0f);   // ifft scale folded in
}

// ------------------------------ FFT helpers --------------------------------
__device__ __forceinline__ float2 cmulf2(float2 a, float2 b) {
    return make_float2(a.x*b.x - a.y*b.y, a.x*b.y + a.y*b.x);
}
template<bool INV>
__device__ __forceinline__ float2 rot90(float2 z) {
    // forward: -i*z ; inverse: +i*z
    return INV ? make_float2(-z.y, z.x) : make_float2(z.y, -z.x);
}
template<bool INV>
__device__ __forceinline__ void dft4(float2 u0, float2 u1, float2 u2, float2 u3,
                                     float2* e) {
    float2 s0 = make_float2(u0.x + u2.x, u0.y + u2.y);
    float2 d0 = make_float2(u0.x - u2.x, u0.y - u2.y);
    float2 s1 = make_float2(u1.x + u3.x, u1.y + u3.y);
    float2 d1 = make_float2(u1.x - u3.x, u1.y - u3.y);
    float2 r1 = rot90<INV>(d1);
    e[0] = make_float2(s0.x + s1.x, s0.y + s1.y);
    e[1] = make_float2(d0.x + r1.x, d0.y + r1.y);
    e[2] = make_float2(s0.x - s1.x, s0.y - s1.y);
    e[3] = make_float2(d0.x - r1.x, d0.y - r1.y);
}

template<bool INV>
__device__ __forceinline__ void bfly8(float2* v, float2* y) {
    float2 E[4], O[4];
    dft4<INV>(v[0], v[2], v[4], v[6], E);
    dft4<INV>(v[1], v[3], v[5], v[7], O);
    const float RS = 0.7071067811865476f;
    O[1] = cmulf2(O[1], make_float2( RS, INV ?  RS : -RS));
    O[2] = rot90<INV>(O[2]);
    O[3] = cmulf2(O[3], make_float2(-RS, INV ?  RS : -RS));
    #pragma unroll
    for (int r = 0; r < 4; r++) {
        y[r]   = make_float2(E[r].x + O[r].x, E[r].y + O[r].y);
        y[r+4] = make_float2(E[r].x - O[r].x, E[r].y - O[r].y);
    }
}

// Apply w^r (w = e^{-/+ i*2*pi*p*STEP/4096}) to y[1..7] via a power chain.
template<bool INV, int STEP>
__device__ __forceinline__ void twiddle8(int p, float2* y) {
    float xang = (float)(p * STEP) * (1.0f / 2048.0f);  // angle / pi
    if (!INV) xang = -xang;
    float s, c;
    sincospif(xang, &s, &c);
    float2 w = make_float2(c, s);
    float2 wr = w;
    y[1] = cmulf2(y[1], wr);
    #pragma unroll
    for (int r = 2; r < 8; r++) {
        wr = cmulf2(wr, w);
        y[r] = cmulf2(y[r], wr);
    }
}

__device__ __forceinline__ int padi(int i) { return i + (i >> 3); }

// Middle Stockham stage (smem -> smem), S = 8 or 64.
template<bool INV, int S>
__device__ __forceinline__ void stage_mid(const float* __restrict__ xr,
                                          const float* __restrict__ xi,
                                          float* __restrict__ yr,
                                          float* __restrict__ yi, int tid) {
    int p = tid / S;
    int q = tid - p * S;
    float2 v[8];
    #pragma unroll
    for (int t = 0; t < 8; t++) {
        int pi = padi(tid + 512 * t);
        v[t] = make_float2(xr[pi], xi[pi]);
    }
    float2 y[8];
    bfly8<INV>(v, y);
    twiddle8<INV, S>(p, y);          // STEP == S for these stages (4096/N)
    #pragma unroll
    for (int r = 0; r < 8; r++) {
        int pi = padi(q + S * (8 * p + r));
        yr[pi] = y[r].x; yi[pi] = y[r].y;
    }
}

// ------------------------------ main kernel --------------------------------
__global__ void __launch_bounds__(NTH, 2)
uvmd_main(const float* __restrict__ x, float* __restrict__ out) {
    int pr = blockIdx.x;
    int b  = pr >> 3;            // batch
    int c  = (pr & 7) << 1;      // even channel of the pair
    int tid = threadIdx.x;

    extern __shared__ float sm[];
    float* Zr = sm;
    float* Zi = Zr + WBUF;
    float* Ar = Zi + WBUF;
    float* Ai = Ar + WBUF;
    float* Br = Ai + WBUF;
    float* Bi = Br + WBUF;

    // ---- forward FFT ----
    // Stage 1 fused with global load: v[t] = z[tid + 512 t]
    {
        const float2* xrow = (const float2*)(x + (size_t)b * TLEN * CCH + c);
        float2 v[8];
        #pragma unroll
        for (int t = 0; t < 8; t++)
            v[t] = xrow[(tid + 512 * t) * (CCH / 2)];
        float2 y[8];
        bfly8<false>(v, y);
        twiddle8<false, 1>(tid, y);
        #pragma unroll
        for (int r = 0; r < 8; r++) {
            int pi = padi(8 * tid + r);      // 9*tid + r : conflict-free
            Ar[pi] = y[r].x; Ai[pi] = y[r].y;
        }
    }
    __syncthreads();
    stage_mid<false, 8 >(Ar, Ai, Br, Bi, tid); __syncthreads();
    stage_mid<false, 64>(Br, Bi, Ar, Ai, tid); __syncthreads();
    // Stage 4 (N=8, S=512, p=0): twiddle-free, write Z
    {
        float2 v[8];
        #pragma unroll
        for (int t = 0; t < 8; t++) {
            int pi = padi(tid + 512 * t);
            v[t] = make_float2(Ar[pi], Ai[pi]);
        }
        float2 y[8];
        bfly8<false>(v, y);
        #pragma unroll
        for (int r = 0; r < 8; r++) {
            int pi = padi(tid + 512 * r);
            Zr[pi] = y[r].x; Zi[pi] = y[r].y;
        }
    }
    __syncthreads();

    // ---- per-mode inverse FFT ----
    #pragma unroll 1
    for (int k = 0; k < KM; k++) {
        // Stage 1 fused with real filter (reads Z, which is never overwritten)
        {
            const float* cc = d_ccx[k];
            float2 v[8];
            #pragma unroll
            for (int t = 0; t < 8; t++) {
                int idx = tid + 512 * t;
                int pi = padi(idx);
                float cf = cc[idx];
                v[t] = make_float2(cf * Zr[pi], cf * Zi[pi]);
            }
            float2 y[8];
            bfly8<true>(v, y);
            twiddle8<true, 1>(tid, y);
            #pragma unroll
            for (int r = 0; r < 8; r++) {
                int pi = padi(8 * tid + r);
                Ar[pi] = y[r].x; Ai[pi] = y[r].y;
            }
        }
        __syncthreads();
        stage_mid<true, 8 >(Ar, Ai, Br, Bi, tid); __syncthreads();
        stage_mid<true, 64>(Br, Bi, Ar, Ai, tid); __syncthreads();
        // Stage 4 fused with global store (twiddle-free):
        // out[b,k, tid+512r, c] = Re, [c+1] = Im
        {
            float2 v[8];
            #pragma unroll
            for (int t = 0; t < 8; t++) {
                int pi = padi(tid + 512 * t);
                v[t] = make_float2(Ar[pi], Ai[pi]);
            }
            float2 y[8];
            bfly8<true>(v, y);
            float2* orow = (float2*)(out + ((size_t)(b * KM + k) * TLEN) * CCH + c);
            #pragma unroll
            for (int r = 0; r < 8; r++)
                orow[(tid + 512 * r) * (CCH / 2)] = y[r];
        }
        __syncthreads();   // A is rewritten by next k's stage 1
    }
}

// ------------------------------ launch -------------------------------------
extern "C" void kernel_launch(void* const* d_in, const int* in_sizes, int n_in,
                              void* d_out, int out_size) {
    const float* x  = (const float*)d_in[0];
    const float* la = (const float*)d_in[1];
    const float* rt = (const float*)d_in[2];
    const float* rw = (const float*)d_in[3];
    float* out = (float*)d_out;

    cudaFuncSetAttribute(uvmd_main, cudaFuncAttributeMaxDynamicSharedMemorySize,
                         SMEM_BYTES);

    uvmd_init<<<32, 128>>>(la, rt, rw);
    uvmd_main<<<64 * 8, NTH, SMEM_BYTES>>>(x, out);
}

// round 10
// speedup vs baseline: 3.5272x; 1.0548x over previous
#include <cuda_runtime.h>
#include <math.h>

// ----------------------------------------------------------------------------
// UVMD block: modes_k = irfft( c_k(f) * rfft(x_row) )
// c_k(f) real + even-extended => acts independently on Re/Im of a complex
// signal. Pair adjacent channels: Z = fft4096(x_c + i x_{c+1});
// z_k = ifft4096(ck .* Z); Re -> ch c, Im -> ch c+1.
// R9: Z lives in REGISTERS (fwd stage-4 output indices == inv stage-1 input
// indices per thread), smem down to 2 ping-pong arrays (73.7 KB);
// init kernel restructured (shared param exps, half-spectrum symmetry,
// fast divide, wide grid).
// ----------------------------------------------------------------------------

#define TLEN 4096
#define KM   8
#define LI   8
#define CCH  16
#define NTH  512

#define WBUF 4608                 // 4096 + 4096/8 padding
#define SMEM_FLOATS (4 * WBUF)
#define SMEM_BYTES  (SMEM_FLOATS * 4)   // 73728 B -> 2 CTAs/SM (reg-limited)

__device__ float d_ccx[KM][4096];       // even-extended c_k(f) / 4096

// ------------------------------ init kernel --------------------------------
// cc(j) depends on j only via m = min(j, 4096-j): compute m = 0..2048 and
// mirror. Parameter transcendentals (80 of them) hoisted to smem per block.
__global__ void uvmd_init(const float* __restrict__ log_alpha,
                          const float* __restrict__ raw_tau,
                          const float* __restrict__ raw_omega) {
    __shared__ float s_alpha[LI * KM];
    __shared__ float s_tau[LI];
    __shared__ float s_omega[KM];
    int t = threadIdx.x;              // 32 threads
    if (t < LI)  s_tau[t] = log1pf(expf(raw_tau[t]));
    if (t >= LI && t < LI + KM)
        s_omega[t - LI] = 0.5f / (1.0f + expf(-raw_omega[t - LI]));
    for (int i = t; i < LI * KM; i += 32)
        s_alpha[i] = expf(log_alpha[i]);
    __syncthreads();

    int m = blockIdx.x * 32 + t;
    if (m > 2048) return;
    float freq = (float)m * (1.0f / 4096.0f);

    float c[KM];
    float g = 0.0f;
    #pragma unroll
    for (int k = 0; k < KM; k++) c[k] = 0.0f;
    #pragma unroll
    for (int l = 0; l < LI; l++) {
        float S = 0.0f;
        #pragma unroll
        for (int k = 0; k < KM; k++) S += c[k];
        float cn[KM];
        float Sn = 0.0f;
        #pragma unroll
        for (int k = 0; k < KM; k++) {
            float df = freq - s_omega[k];
            float den = 1.0f + 2.0f * s_alpha[l*KM + k] * df * df;
            cn[k] = __fdividef(1.0f - (S - c[k]) + 0.5f * g, den);
            Sn += cn[k];
        }
        g += s_tau[l] * (1.0f - Sn);
        #pragma unroll
        for (int k = 0; k < KM; k++) c[k] = cn[k];
    }
    int j2 = (4096 - m) & 4095;       // mirror bin (m=0 -> 0, m=2048 -> 2048)
    #pragma unroll
    for (int k = 0; k < KM; k++) {
        float v = c[k] * (1.0f / 4096.0f);   // ifft scale folded in
        d_ccx[k][m]  = v;
        d_ccx[k][j2] = v;
    }
}

// ------------------------------ FFT helpers --------------------------------
__device__ __forceinline__ float2 cmulf2(float2 a, float2 b) {
    return make_float2(a.x*b.x - a.y*b.y, a.x*b.y + a.y*b.x);
}
template<bool INV>
__device__ __forceinline__ float2 rot90(float2 z) {
    // forward: -i*z ; inverse: +i*z
    return INV ? make_float2(-z.y, z.x) : make_float2(z.y, -z.x);
}
template<bool INV>
__device__ __forceinline__ void dft4(float2 u0, float2 u1, float2 u2, float2 u3,
                                     float2* e) {
    float2 s0 = make_float2(u0.x + u2.x, u0.y + u2.y);
    float2 d0 = make_float2(u0.x - u2.x, u0.y - u2.y);
    float2 s1 = make_float2(u1.x + u3.x, u1.y + u3.y);
    float2 d1 = make_float2(u1.x - u3.x, u1.y - u3.y);
    float2 r1 = rot90<INV>(d1);
    e[0] = make_float2(s0.x + s1.x, s0.y + s1.y);
    e[1] = make_float2(d0.x + r1.x, d0.y + r1.y);
    e[2] = make_float2(s0.x - s1.x, s0.y - s1.y);
    e[3] = make_float2(d0.x - s1.x + s1.x - r1.x, d0.y - r1.y);  // placeholder
}

template<bool INV>
__device__ __forceinline__ void dft4b(float2 u0, float2 u1, float2 u2, float2 u3,
                                      float2* e) {
    float2 s0 = make_float2(u0.x + u2.x, u0.y + u2.y);
    float2 d0 = make_float2(u0.x - u2.x, u0.y - u2.y);
    float2 s1 = make_float2(u1.x + u3.x, u1.y + u3.y);
    float2 d1 = make_float2(u1.x - u3.x, u1.y - u3.y);
    float2 r1 = rot90<INV>(d1);
    e[0] = make_float2(s0.x + s1.x, s0.y + s1.y);
    e[1] = make_float2(d0.x + r1.x, d0.y + r1.y);
    e[2] = make_float2(s0.x - s1.x, s0.y - s1.y);
    e[3] = make_float2(d0.x - r1.x, d0.y - r1.y);
}

template<bool INV>
__device__ __forceinline__ void bfly8(float2* v, float2* y) {
    float2 E[4], O[4];
    dft4b<INV>(v[0], v[2], v[4], v[6], E);
    dft4b<INV>(v[1], v[3], v[5], v[7], O);
    const float RS = 0.7071067811865476f;
    O[1] = cmulf2(O[1], make_float2( RS, INV ?  RS : -RS));
    O[2] = rot90<INV>(O[2]);
    O[3] = cmulf2(O[3], make_float2(-RS, INV ?  RS : -RS));
    #pragma unroll
    for (int r = 0; r < 4; r++) {
        y[r]   = make_float2(E[r].x + O[r].x, E[r].y + O[r].y);
        y[r+4] = make_float2(E[r].x - O[r].x, E[r].y - O[r].y);
    }
}

// Apply w^r (w = e^{-/+ i*2*pi*p*STEP/4096}) to y[1..7] via a power chain.
template<bool INV, int STEP>
__device__ __forceinline__ void twiddle8(int p, float2* y) {
    float xang = (float)(p * STEP) * (1.0f / 2048.0f);  // angle / pi
    if (!INV) xang = -xang;
    float s, c;
    sincospif(xang, &s, &c);
    float2 w = make_float2(c, s);
    float2 wr = w;
    y[1] = cmulf2(y[1], wr);
    #pragma unroll
    for (int r = 2; r < 8; r++) {
        wr = cmulf2(wr, w);
        y[r] = cmulf2(y[r], wr);
    }
}

__device__ __forceinline__ int padi(int i) { return i + (i >> 3); }

// Middle Stockham stage (smem -> smem), S = 8 or 64.
template<bool INV, int S>
__device__ __forceinline__ void stage_mid(const float* __restrict__ xr,
                                          const float* __restrict__ xi,
                                          float* __restrict__ yr,
                                          float* __restrict__ yi, int tid) {
    int p = tid / S;
    int q = tid - p * S;
    float2 v[8];
    #pragma unroll
    for (int t = 0; t < 8; t++) {
        int pi = padi(tid + 512 * t);
        v[t] = make_float2(xr[pi], xi[pi]);
    }
    float2 y[8];
    bfly8<INV>(v, y);
    twiddle8<INV, S>(p, y);          // STEP == S for these stages (4096/N)
    #pragma unroll
    for (int r = 0; r < 8; r++) {
        int pi = padi(q + S * (8 * p + r));
        yr[pi] = y[r].x; yi[pi] = y[r].y;
    }
}

// ------------------------------ main kernel --------------------------------
__global__ void __launch_bounds__(NTH, 2)
uvmd_main(const float* __restrict__ x, float* __restrict__ out) {
    int pr = blockIdx.x;
    int b  = pr >> 3;            // batch
    int c  = (pr & 7) << 1;      // even channel of the pair
    int tid = threadIdx.x;

    extern __shared__ float sm[];
    float* Ar = sm;
    float* Ai = Ar + WBUF;
    float* Br = Ai + WBUF;
    float* Bi = Br + WBUF;

    // ---- forward FFT ----
    // Stage 1 fused with global load: v[t] = z[tid + 512 t]
    {
        const float2* xrow = (const float2*)(x + (size_t)b * TLEN * CCH + c);
        float2 v[8];
        #pragma unroll
        for (int t = 0; t < 8; t++)
            v[t] = xrow[(tid + 512 * t) * (CCH / 2)];
        float2 y[8];
        bfly8<false>(v, y);
        twiddle8<false, 1>(tid, y);
        #pragma unroll
        for (int r = 0; r < 8; r++) {
            int pi = padi(8 * tid + r);      // 9*tid + r : conflict-free
            Ar[pi] = y[r].x; Ai[pi] = y[r].y;
        }
    }
    __syncthreads();
    stage_mid<false, 8 >(Ar, Ai, Br, Bi, tid); __syncthreads();
    stage_mid<false, 64>(Br, Bi, Ar, Ai, tid); __syncthreads();

    // Stage 4 (N=8, S=512, p=0): twiddle-free; output kept in REGISTERS.
    // zf[r] = Z[tid + 512 r] — exactly what inverse stage 1 consumes.
    float2 zf[8];
    {
        float2 v[8];
        #pragma unroll
        for (int t = 0; t < 8; t++) {
            int pi = padi(tid + 512 * t);
            v[t] = make_float2(Ar[pi], Ai[pi]);
        }
        bfly8<false>(v, zf);
    }
    __syncthreads();      // all reads of A done before mode loop overwrites it

    // ---- per-mode inverse FFT ----
    #pragma unroll 1
    for (int k = 0; k < KM; k++) {
        // Stage 1: filter (registers) -> A.  p = tid, S = 1.
        {
            const float* cc = d_ccx[k];
            float2 v[8];
            #pragma unroll
            for (int t = 0; t < 8; t++) {
                float cf = __ldg(&cc[tid + 512 * t]);
                v[t] = make_float2(cf * zf[t].x, cf * zf[t].y);
            }
            float2 y[8];
            bfly8<true>(v, y);
            twiddle8<true, 1>(tid, y);
            #pragma unroll
            for (int r = 0; r < 8; r++) {
                int pi = padi(8 * tid + r);
                Ar[pi] = y[r].x; Ai[pi] = y[r].y;
            }
        }
        __syncthreads();
        stage_mid<true, 8 >(Ar, Ai, Br, Bi, tid); __syncthreads();
        stage_mid<true, 64>(Br, Bi, Ar, Ai, tid); __syncthreads();
        // Stage 4 fused with global store (twiddle-free):
        // out[b,k, tid+512r, c] = Re, [c+1] = Im
        {
            float2 v[8];
            #pragma unroll
            for (int t = 0; t < 8; t++) {
                int pi = padi(tid + 512 * t);
                v[t] = make_float2(Ar[pi], Ai[pi]);
            }
            float2 y[8];
            bfly8<true>(v, y);
            float2* orow = (float2*)(out + ((size_t)(b * KM + k) * TLEN) * CCH + c);
            #pragma unroll
            for (int r = 0; r < 8; r++)
                orow[(tid + 512 * r) * (CCH / 2)] = y[r];
        }
        __syncthreads();   // A is rewritten by next k's stage 1
    }
}

// ------------------------------ launch -------------------------------------
extern "C" void kernel_launch(void* const* d_in, const int* in_sizes, int n_in,
                              void* d_out, int out_size) {
    const float* x  = (const float*)d_in[0];
    const float* la = (const float*)d_in[1];
    const float* rt = (const float*)d_in[2];
    const float* rw = (const float*)d_in[3];
    float* out = (float*)d_out;

    cudaFuncSetAttribute(uvmd_main, cudaFuncAttributeMaxDynamicSharedMemorySize,
                         SMEM_BYTES);

    uvmd_init<<<65, 32>>>(la, rt, rw);            // 65*32 = 2080 >= 2049 bins
    uvmd_main<<<64 * 8, NTH, SMEM_BYTES>>>(x, out);
}

// round 16
// speedup vs baseline: 3.5592x; 1.0091x over previous
#include <cuda_runtime.h>
#include <cuda.h>
#include <math.h>
#include <string.h>

// ----------------------------------------------------------------------------
// UVMD block: modes_k = irfft( c_k(f) * rfft(x_row) )
// c_k(f) real + even-extended => acts independently on Re/Im of a complex
// signal. Pair adjacent channels: Z = fft4096(x_c + i x_{c+1});
// z_k = ifft4096(ck .* Z); Re -> ch c, Im -> ch c+1.
// R15: 4 channels (2 pairs) per CTA, grid 256 = single wave; stage-4 results
// staged in smem (t-major, 4 channels contiguous) and written out either by
// async TMA bulk-tensor stores (overlapped with next mode's FFT) or, as a
// fallback, by coalesced float4 copies from the same staging tile.
// ----------------------------------------------------------------------------

#define TLEN 4096
#define KM   8
#define LI   8
#define CCH  16
#define NTH  512

#define WBUF 4608                 // 4096 + 4096/8 padding
#define STG_F2 4096               // staging: 2048 t x 2 float2 (32 KB)
#define SMEM_BYTES (4*WBUF*4 + STG_F2*8)   // 73728 + 32768 = 106496

__device__ float d_ccx[KM][4096];       // even-extended c_k(f) / 4096

// ------------------------------ init kernel --------------------------------
__global__ void uvmd_init(const float* __restrict__ log_alpha,
                          const float* __restrict__ raw_tau,
                          const float* __restrict__ raw_omega) {
    __shared__ float s_alpha[LI * KM];
    __shared__ float s_tau[LI];
    __shared__ float s_omega[KM];
    int t = threadIdx.x;              // 32 threads
    if (t < LI)  s_tau[t] = log1pf(expf(raw_tau[t]));
    if (t >= LI && t < LI + KM)
        s_omega[t - LI] = 0.5f / (1.0f + expf(-raw_omega[t - LI]));
    for (int i = t; i < LI * KM; i += 32)
        s_alpha[i] = expf(log_alpha[i]);
    __syncthreads();

    int m = blockIdx.x * 32 + t;
    if (m > 2048) return;
    float freq = (float)m * (1.0f / 4096.0f);

    float c[KM];
    float g = 0.0f;
    #pragma unroll
    for (int k = 0; k < KM; k++) c[k] = 0.0f;
    #pragma unroll
    for (int l = 0; l < LI; l++) {
        float S = 0.0f;
        #pragma unroll
        for (int k = 0; k < KM; k++) S += c[k];
        float cn[KM];
        float Sn = 0.0f;
        #pragma unroll
        for (int k = 0; k < KM; k++) {
            float df = freq - s_omega[k];
            float den = 1.0f + 2.0f * s_alpha[l*KM + k] * df * df;
            cn[k] = __fdividef(1.0f - (S - c[k]) + 0.5f * g, den);
            Sn += cn[k];
        }
        g += s_tau[l] * (1.0f - Sn);
        #pragma unroll
        for (int k = 0; k < KM; k++) c[k] = cn[k];
    }
    int j2 = (4096 - m) & 4095;       // mirror bin
    #pragma unroll
    for (int k = 0; k < KM; k++) {
        float v = c[k] * (1.0f / 4096.0f);   // ifft scale folded in
        d_ccx[k][m]  = v;
        d_ccx[k][j2] = v;
    }
}

// ------------------------------ FFT helpers --------------------------------
__device__ __forceinline__ float2 cmulf2(float2 a, float2 b) {
    return make_float2(a.x*b.x - a.y*b.y, a.x*b.y + a.y*b.x);
}
template<bool INV>
__device__ __forceinline__ float2 rot90(float2 z) {
    return INV ? make_float2(-z.y, z.x) : make_float2(z.y, -z.x);
}
template<bool INV>
__device__ __forceinline__ void dft4b(float2 u0, float2 u1, float2 u2, float2 u3,
                                      float2* e) {
    float2 s0 = make_float2(u0.x + u2.x, u0.y + u2.y);
    float2 d0 = make_float2(u0.x - u2.x, u0.y - u2.y);
    float2 s1 = make_float2(u1.x + u3.x, u1.y + u3.y);
    float2 d1 = make_float2(u1.x - u3.x, u1.y - u3.y);
    float2 r1 = rot90<INV>(d1);
    e[0] = make_float2(s0.x + s1.x, s0.y + s1.y);
    e[1] = make_float2(d0.x + r1.x, d0.y + r1.y);
    e[2] = make_float2(s0.x - s1.x, s0.y - s1.y);
    e[3] = make_float2(d0.x - r1.x, d0.y - r1.y);
}
template<bool INV>
__device__ __forceinline__ void bfly8(float2* v, float2* y) {
    float2 E[4], O[4];
    dft4b<INV>(v[0], v[2], v[4], v[6], E);
    dft4b<INV>(v[1], v[3], v[5], v[7], O);
    const float RS = 0.7071067811865476f;
    O[1] = cmulf2(O[1], make_float2( RS, INV ?  RS : -RS));
    O[2] = rot90<INV>(O[2]);
    O[3] = cmulf2(O[3], make_float2(-RS, INV ?  RS : -RS));
    #pragma unroll
    for (int r = 0; r < 4; r++) {
        y[r]   = make_float2(E[r].x + O[r].x, E[r].y + O[r].y);
        y[r+4] = make_float2(E[r].x - O[r].x, E[r].y - O[r].y);
    }
}
// Apply w^r (w = e^{-/+ i*2*pi*p*STEP/4096}) to y[1..7] via a power chain.
template<bool INV, int STEP>
__device__ __forceinline__ void twiddle8(int p, float2* y) {
    float xang = (float)(p * STEP) * (1.0f / 2048.0f);  // angle / pi
    if (!INV) xang = -xang;
    float s, c;
    sincospif(xang, &s, &c);
    float2 w = make_float2(c, s);
    float2 wr = w;
    y[1] = cmulf2(y[1], wr);
    #pragma unroll
    for (int r = 2; r < 8; r++) {
        wr = cmulf2(wr, w);
        y[r] = cmulf2(y[r], wr);
    }
}
__device__ __forceinline__ int padi(int i) { return i + (i >> 3); }

// Middle Stockham stage (smem -> smem), S = 8 or 64.
template<bool INV, int S>
__device__ __forceinline__ void stage_mid(const float* __restrict__ xr,
                                          const float* __restrict__ xi,
                                          float* __restrict__ yr,
                                          float* __restrict__ yi, int tid) {
    int p = tid / S;
    int q = tid - p * S;
    float2 v[8];
    #pragma unroll
    for (int t = 0; t < 8; t++) {
        int pi = padi(tid + 512 * t);
        v[t] = make_float2(xr[pi], xi[pi]);
    }
    float2 y[8];
    bfly8<INV>(v, y);
    twiddle8<INV, S>(p, y);
    #pragma unroll
    for (int r = 0; r < 8; r++) {
        int pi = padi(q + S * (8 * p + r));
        yr[pi] = y[r].x; yi[pi] = y[r].y;
    }
}

// ------------------------------ TMA helpers --------------------------------
__device__ __forceinline__ void tma_st3d(const CUtensorMap* tm, int cx, int cy,
                                         int cz, unsigned smem) {
    asm volatile(
        "cp.async.bulk.tensor.3d.global.shared::cta.tile.bulk_group "
        "[%0, {%1, %2, %3}], [%4];"
        :: "l"(tm), "r"(cx), "r"(cy), "r"(cz), "r"(smem) : "memory");
}
__device__ __forceinline__ void tma_commit() {
    asm volatile("cp.async.bulk.commit_group;" ::: "memory");
}
__device__ __forceinline__ void tma_wait0() {
    asm volatile("cp.async.bulk.wait_group 0;" ::: "memory");
}
__device__ __forceinline__ void fence_async_smem() {
    asm volatile("fence.proxy.async.shared::cta;" ::: "memory");
}
__device__ __forceinline__ unsigned smem_u32(const void* p) {
    unsigned a;
    asm("{ .reg .u64 t; cvta.to.shared.u64 t, %1; cvt.u32.u64 %0, t; }"
        : "=r"(a) : "l"(p));
    return a;
}

// ------------------------------ main kernel --------------------------------
// CTA = 4 channels (2 complex pairs) of one batch. grid = 64*4 = 256.
__global__ void __launch_bounds__(NTH, 2)
uvmd_main(const float* __restrict__ x, float* __restrict__ out,
          const __grid_constant__ CUtensorMap tmap, int use_tma) {
    int pr = blockIdx.x;
    int b  = pr >> 2;            // batch
    int cg = pr & 3;             // channel group: channels 4*cg .. 4*cg+3
    int c0 = cg << 2;
    int tid = threadIdx.x;

    extern __shared__ float sm[];
    float* Ar = sm;
    float* Ai = Ar + WBUF;
    float* Br = Ai + WBUF;
    float* Bi = Br + WBUF;
    float2* stag = (float2*)(sm + 4 * WBUF);   // [chunk(8)][off(256)][pair(2)]
    float4* stag4 = (float4*)stag;             // stag4[tp] = t row, 4 channels

    // ---- forward FFTs for both pairs; spectra kept in registers ----
    float2 zf0[8], zf1[8];
    #pragma unroll
    for (int p = 0; p < 2; p++) {
        const float2* xrow =
            (const float2*)(x + (size_t)b * TLEN * CCH + c0 + 2 * p);
        float2 v[8], y[8];
        #pragma unroll
        for (int t = 0; t < 8; t++)
            v[t] = xrow[(tid + 512 * t) * (CCH / 2)];
        bfly8<false>(v, y);
        twiddle8<false, 1>(tid, y);
        #pragma unroll
        for (int r = 0; r < 8; r++) {
            int pi = padi(8 * tid + r);
            Ar[pi] = y[r].x; Ai[pi] = y[r].y;
        }
        __syncthreads();
        stage_mid<false, 8 >(Ar, Ai, Br, Bi, tid); __syncthreads();
        stage_mid<false, 64>(Br, Bi, Ar, Ai, tid); __syncthreads();
        #pragma unroll
        for (int t = 0; t < 8; t++) {
            int pi = padi(tid + 512 * t);
            v[t] = make_float2(Ar[pi], Ai[pi]);
        }
        if (p == 0) bfly8<false>(v, zf0); else bfly8<false>(v, zf1);
        __syncthreads();          // A free for next pair / mode loop
    }

    // ---- per-mode inverse FFTs ----
    float2 keep[2][4];            // r = 4..7 of stage-4, parked per pair
    #pragma unroll 1
    for (int k = 0; k < KM; k++) {
        const float* cc = d_ccx[k];
        #pragma unroll
        for (int p = 0; p < 2; p++) {
            // Stage 1: filter * Z(regs) -> A
            {
                float2 v[8], y[8];
                #pragma unroll
                for (int t = 0; t < 8; t++) {
                    float cf = __ldg(&cc[tid + 512 * t]);
                    float2 z = (p == 0) ? zf0[t] : zf1[t];
                    v[t] = make_float2(cf * z.x, cf * z.y);
                }
                bfly8<true>(v, y);
                twiddle8<true, 1>(tid, y);
                #pragma unroll
                for (int r = 0; r < 8; r++) {
                    int pi = padi(8 * tid + r);
                    Ar[pi] = y[r].x; Ai[pi] = y[r].y;
                }
            }
            __syncthreads();
            stage_mid<true, 8 >(Ar, Ai, Br, Bi, tid); __syncthreads();
            stage_mid<true, 64>(Br, Bi, Ar, Ai, tid); __syncthreads();
            // Stage 4 (twiddle-free) -> staging (half 1) + parked regs
            {
                float2 v[8], y[8];
                #pragma unroll
                for (int t = 0; t < 8; t++) {
                    int pi = padi(tid + 512 * t);
                    v[t] = make_float2(Ar[pi], Ai[pi]);
                }
                bfly8<true>(v, y);
                if (p == 0 && use_tma) {   // staging reused: drain prev TMA
                    if (tid == 0) tma_wait0();
                    __syncthreads();
                }
                #pragma unroll
                for (int r = 0; r < 4; r++) {   // t < 2048 half
                    int tp = tid + 512 * r;
                    stag[((tp >> 8) << 9) + ((tp & 255) << 1) + p] = y[r];
                }
                #pragma unroll
                for (int r = 0; r < 4; r++) keep[p][r] = y[r + 4];
            }
            __syncthreads();      // A free; staging half-1 visible
        }

        int bk = b * KM + k;
        if (use_tma) {
            // TMA store half 1 (t in [0, 2048))
            fence_async_smem();
            __syncthreads();
            unsigned sbase = smem_u32(stag);
            if (tid == 0) {
                #pragma unroll
                for (int j = 0; j < 8; j++)
                    tma_st3d(&tmap, c0, j * 256, bk, sbase + j * 4096);
                tma_commit();
                tma_wait0();      // staging reused immediately for half 2
            }
            __syncthreads();
            // Stage half 2 from parked registers
            #pragma unroll
            for (int p = 0; p < 2; p++)
                #pragma unroll
                for (int r = 0; r < 4; r++) {
                    int tp = tid + 512 * r;   // local index within half
                    stag[((tp >> 8) << 9) + ((tp & 255) << 1) + p] = keep[p][r];
                }
            fence_async_smem();
            __syncthreads();
            if (tid == 0) {
                #pragma unroll
                for (int j = 0; j < 8; j++)
                    tma_st3d(&tmap, c0, 2048 + j * 256, bk, sbase + j * 4096);
                tma_commit();
                // drained at next mode's pair-0 stage-4 (overlaps s1..s3)
            }
            // no barrier needed: staging untouched until after that wait
        } else {
            // Fallback: coalesced float4 copy from staging.
            // stag4[tp] holds t = tp, channels c0..c0+3.
            float4* og = (float4*)(out + ((size_t)bk * TLEN) * CCH + c0);
            #pragma unroll
            for (int r = 0; r < 4; r++) {
                int tp = tid + 512 * r;
                og[(size_t)tp * (CCH / 4)] = stag4[tp];
            }
            __syncthreads();
            // half 2 from parked regs
            #pragma unroll
            for (int p = 0; p < 2; p++)
                #pragma unroll
                for (int r = 0; r < 4; r++) {
                    int tp = tid + 512 * r;
                    stag[((tp >> 8) << 9) + ((tp & 255) << 1) + p] = keep[p][r];
                }
            __syncthreads();
            #pragma unroll
            for (int r = 0; r < 4; r++) {
                int tp = tid + 512 * r;
                og[(size_t)(2048 + tp) * (CCH / 4)] = stag4[tp];
            }
            __syncthreads();
        }
    }
    if (use_tma) {                // drain last group before CTA exit
        if (tid == 0) tma_wait0();
        __syncthreads();
    }
}

// ------------------------------ launch -------------------------------------
typedef CUresult (*EncodeTiledFn)(
    CUtensorMap*, CUtensorMapDataType, cuuint32_t, void*,
    const cuuint64_t*, const cuuint64_t*, const cuuint32_t*, const cuuint32_t*,
    CUtensorMapInterleave, CUtensorMapSwizzle, CUtensorMapL2promotion,
    CUtensorMapFloatOOBfill);

extern "C" void kernel_launch(void* const* d_in, const int* in_sizes, int n_in,
                              void* d_out, int out_size) {
    const float* x  = (const float*)d_in[0];
    const float* la = (const float*)d_in[1];
    const float* rt = (const float*)d_in[2];
    const float* rw = (const float*)d_in[3];
    float* out = (float*)d_out;

    // Build TMA descriptor for out viewed as (C=16, T=4096, B*K=512) f32.
    CUtensorMap tmap;
    memset(&tmap, 0, sizeof(tmap));
    int use_tma = 0;
    void* sym = nullptr;
    cudaDriverEntryPointQueryResult qr = cudaDriverEntryPointSymbolNotFound;
    cudaError_t qe = cudaGetDriverEntryPointByVersion(
        "cuTensorMapEncodeTiled", &sym, 12000, cudaEnableDefault, &qr);
    if (qe == cudaSuccess && sym && qr == cudaDriverEntryPointSuccess) {
        cuuint64_t dims[3]    = {16, 4096, 512};
        cuuint64_t strides[2] = {16 * 4, (cuuint64_t)4096 * 16 * 4};
        cuuint32_t box[3]     = {4, 256, 1};
        cuuint32_t estr[3]    = {1, 1, 1};
        EncodeTiledFn enc = (EncodeTiledFn)sym;
        CUresult r = enc(&tmap, CU_TENSOR_MAP_DATA_TYPE_FLOAT32, 3, out,
                         dims, strides, box, estr,
                         CU_TENSOR_MAP_INTERLEAVE_NONE,
                         CU_TENSOR_MAP_SWIZZLE_NONE,
                         CU_TENSOR_MAP_L2_PROMOTION_L2_128B,
                         CU_TENSOR_MAP_FLOAT_OOB_FILL_NONE);
        use_tma = (r == CUDA_SUCCESS) ? 1 : 0;
    }

    cudaFuncSetAttribute(uvmd_main, cudaFuncAttributeMaxDynamicSharedMemorySize,
                         SMEM_BYTES);

    uvmd_init<<<65, 32>>>(la, rt, rw);
    uvmd_main<<<64 * 4, NTH, SMEM_BYTES>>>(x, out, tmap, use_tma);
}

// round 17
// speedup vs baseline: 3.7324x; 1.0487x over previous
#include <cuda_runtime.h>
#include <cuda.h>
#include <math.h>
#include <string.h>

// ----------------------------------------------------------------------------
// UVMD block: modes_k = irfft( c_k(f) * rfft(x_row) )
// c_k(f) real + even-extended => acts independently on Re/Im of a complex
// signal. Pair adjacent channels: Z = fft4096(x_c + i x_{c+1});
// z_k = ifft4096(ck .* Z); Re -> ch c, Im -> ch c+1.
// R17: the 18 FFTs per CTA run as a pipelined chain: stage-4 of FFT n is
// fused with stage-1 of FFT n+1 (independent ping-pong buffers), and all
// TMA staging/commit/drain work is folded into compute periods. Steady
// state: 3 barrier periods per FFT instead of 4-5.
// ----------------------------------------------------------------------------

#define TLEN 4096
#define KM   8
#define LI   8
#define CCH  16
#define NTH  512

#define WBUF 4608                 // 4096 + 4096/8 padding
#define STG_F2 4096               // staging: 2048 t x 2 float2 (32 KB)
#define SMEM_BYTES (4*WBUF*4 + STG_F2*8)   // 73728 + 32768 = 106496

__device__ float d_ccx[KM][4096];       // even-extended c_k(f) / 4096

// ------------------------------ init kernel --------------------------------
__global__ void uvmd_init(const float* __restrict__ log_alpha,
                          const float* __restrict__ raw_tau,
                          const float* __restrict__ raw_omega) {
    __shared__ float s_alpha[LI * KM];
    __shared__ float s_tau[LI];
    __shared__ float s_omega[KM];
    int t = threadIdx.x;              // 32 threads
    if (t < LI)  s_tau[t] = log1pf(expf(raw_tau[t]));
    if (t >= LI && t < LI + KM)
        s_omega[t - LI] = 0.5f / (1.0f + expf(-raw_omega[t - LI]));
    for (int i = t; i < LI * KM; i += 32)
        s_alpha[i] = expf(log_alpha[i]);
    __syncthreads();

    int m = blockIdx.x * 32 + t;
    if (m > 2048) return;
    float freq = (float)m * (1.0f / 4096.0f);

    float c[KM];
    float g = 0.0f;
    #pragma unroll
    for (int k = 0; k < KM; k++) c[k] = 0.0f;
    #pragma unroll
    for (int l = 0; l < LI; l++) {
        float S = 0.0f;
        #pragma unroll
        for (int k = 0; k < KM; k++) S += c[k];
        float cn[KM];
        float Sn = 0.0f;
        #pragma unroll
        for (int k = 0; k < KM; k++) {
            float df = freq - s_omega[k];
            float den = 1.0f + 2.0f * s_alpha[l*KM + k] * df * df;
            cn[k] = __fdividef(1.0f - (S - c[k]) + 0.5f * g, den);
            Sn += cn[k];
        }
        g += s_tau[l] * (1.0f - Sn);
        #pragma unroll
        for (int k = 0; k < KM; k++) c[k] = cn[k];
    }
    int j2 = (4096 - m) & 4095;       // mirror bin
    #pragma unroll
    for (int k = 0; k < KM; k++) {
        float v = c[k] * (1.0f / 4096.0f);   // ifft scale folded in
        d_ccx[k][m]  = v;
        d_ccx[k][j2] = v;
    }
}

// ------------------------------ FFT helpers --------------------------------
__device__ __forceinline__ float2 cmulf2(float2 a, float2 b) {
    return make_float2(a.x*b.x - a.y*b.y, a.x*b.y + a.y*b.x);
}
template<bool INV>
__device__ __forceinline__ float2 rot90(float2 z) {
    return INV ? make_float2(-z.y, z.x) : make_float2(z.y, -z.x);
}
template<bool INV>
__device__ __forceinline__ void dft4b(float2 u0, float2 u1, float2 u2, float2 u3,
                                      float2* e) {
    float2 s0 = make_float2(u0.x + u2.x, u0.y + u2.y);
    float2 d0 = make_float2(u0.x - u2.x, u0.y - u2.y);
    float2 s1 = make_float2(u1.x + u3.x, u1.y + u3.y);
    float2 d1 = make_float2(u1.x - u3.x, u1.y - u3.y);
    float2 r1 = rot90<INV>(d1);
    e[0] = make_float2(s0.x + s1.x, s0.y + s1.y);
    e[1] = make_float2(d0.x + r1.x, d0.y + r1.y);
    e[2] = make_float2(s0.x - s1.x, s0.y - s1.y);
    e[3] = make_float2(d0.x - r1.x, d0.y - r1.y);
}
template<bool INV>
__device__ __forceinline__ void bfly8(float2* v, float2* y) {
    float2 E[4], O[4];
    dft4b<INV>(v[0], v[2], v[4], v[6], E);
    dft4b<INV>(v[1], v[3], v[5], v[7], O);
    const float RS = 0.7071067811865476f;
    O[1] = cmulf2(O[1], make_float2( RS, INV ?  RS : -RS));
    O[2] = rot90<INV>(O[2]);
    O[3] = cmulf2(O[3], make_float2(-RS, INV ?  RS : -RS));
    #pragma unroll
    for (int r = 0; r < 4; r++) {
        y[r]   = make_float2(E[r].x + O[r].x, E[r].y + O[r].y);
        y[r+4] = make_float2(E[r].x - O[r].x, E[r].y - O[r].y);
    }
}
// Apply w^r to y[1..7]; powers built log-depth (depth 3, not a 7-chain).
template<bool INV, int STEP>
__device__ __forceinline__ void twiddle8(int p, float2* y) {
    float xang = (float)(p * STEP) * (1.0f / 2048.0f);  // angle / pi
    if (!INV) xang = -xang;
    float s, c;
    sincospif(xang, &s, &c);
    float2 w1 = make_float2(c, s);
    float2 w2 = cmulf2(w1, w1);
    float2 w4 = cmulf2(w2, w2);
    float2 w3 = cmulf2(w2, w1);
    float2 w5 = cmulf2(w4, w1);
    float2 w6 = cmulf2(w4, w2);
    float2 w7 = cmulf2(w4, w3);
    y[1] = cmulf2(y[1], w1);
    y[2] = cmulf2(y[2], w2);
    y[3] = cmulf2(y[3], w3);
    y[4] = cmulf2(y[4], w4);
    y[5] = cmulf2(y[5], w5);
    y[6] = cmulf2(y[6], w6);
    y[7] = cmulf2(y[7], w7);
}
__device__ __forceinline__ int padi(int i) { return i + (i >> 3); }

// Middle Stockham stage (smem -> smem), S = 8 or 64.
template<bool INV, int S>
__device__ __forceinline__ void stage_mid(const float* __restrict__ xr,
                                          const float* __restrict__ xi,
                                          float* __restrict__ yr,
                                          float* __restrict__ yi, int tid) {
    int p = tid / S;
    int q = tid - p * S;
    float2 v[8];
    #pragma unroll
    for (int t = 0; t < 8; t++) {
        int pi = padi(tid + 512 * t);
        v[t] = make_float2(xr[pi], xi[pi]);
    }
    float2 y[8];
    bfly8<INV>(v, y);
    twiddle8<INV, S>(p, y);
    #pragma unroll
    for (int r = 0; r < 8; r++) {
        int pi = padi(q + S * (8 * p + r));
        yr[pi] = y[r].x; yi[pi] = y[r].y;
    }
}

// Stage-1 of an inverse FFT: filter * Z (registers) -> dst buffer.
__device__ __forceinline__ void s1_from_zf(const float2* zf,
                                           const float* __restrict__ cc,
                                           float* __restrict__ dr,
                                           float* __restrict__ di, int tid) {
    float2 v[8], y[8];
    #pragma unroll
    for (int t = 0; t < 8; t++) {
        float cf = __ldg(&cc[tid + 512 * t]);
        v[t] = make_float2(cf * zf[t].x, cf * zf[t].y);
    }
    bfly8<true>(v, y);
    twiddle8<true, 1>(tid, y);
    #pragma unroll
    for (int r = 0; r < 8; r++) {
        int pi = padi(8 * tid + r);
        dr[pi] = y[r].x; di[pi] = y[r].y;
    }
}

// Stage-1 of the forward FFT fused with the global load.
__device__ __forceinline__ void s1_fwd(const float2* __restrict__ xrow,
                                       float* __restrict__ dr,
                                       float* __restrict__ di, int tid) {
    float2 v[8], y[8];
    #pragma unroll
    for (int t = 0; t < 8; t++)
        v[t] = xrow[(tid + 512 * t) * (CCH / 2)];
    bfly8<false>(v, y);
    twiddle8<false, 1>(tid, y);
    #pragma unroll
    for (int r = 0; r < 8; r++) {
        int pi = padi(8 * tid + r);
        dr[pi] = y[r].x; di[pi] = y[r].y;
    }
}

// Stage-4 read+butterfly (twiddle-free): src buffer -> y registers.
template<bool INV>
__device__ __forceinline__ void s4_read(const float* __restrict__ sr,
                                        const float* __restrict__ si,
                                        float2* y, int tid) {
    float2 v[8];
    #pragma unroll
    for (int t = 0; t < 8; t++) {
        int pi = padi(tid + 512 * t);
        v[t] = make_float2(sr[pi], si[pi]);
    }
    bfly8<INV>(v, y);
}

// ------------------------------ TMA helpers --------------------------------
__device__ __forceinline__ void tma_st3d(const CUtensorMap* tm, int cx, int cy,
                                         int cz, unsigned smem) {
    asm volatile(
        "cp.async.bulk.tensor.3d.global.shared::cta.tile.bulk_group "
        "[%0, {%1, %2, %3}], [%4];"
        :: "l"(tm), "r"(cx), "r"(cy), "r"(cz), "r"(smem) : "memory");
}
__device__ __forceinline__ void tma_commit() {
    asm volatile("cp.async.bulk.commit_group;" ::: "memory");
}
__device__ __forceinline__ void tma_wait0() {
    asm volatile("cp.async.bulk.wait_group 0;" ::: "memory");
}
__device__ __forceinline__ void fence_async_smem() {
    asm volatile("fence.proxy.async.shared::cta;" ::: "memory");
}
__device__ __forceinline__ unsigned smem_u32(const void* p) {
    unsigned a;
    asm("{ .reg .u64 t; cvta.to.shared.u64 t, %1; cvt.u32.u64 %0, t; }"
        : "=r"(a) : "l"(p));
    return a;
}

// ------------------------------ main kernel --------------------------------
// CTA = 4 channels (2 complex pairs) of one batch. grid = 64*4 = 256.
// FFT chain (18 FFTs): fwd p0, fwd p1, then (mode k, pair p) for k=0..7.
// Buffer parity alternates per FFT: even FFT uses A->B->A, odd uses B->A->B.
__global__ void __launch_bounds__(NTH, 2)
uvmd_main(const float* __restrict__ x, float* __restrict__ out,
          const __grid_constant__ CUtensorMap tmap, int use_tma) {
    int pr = blockIdx.x;
    int b  = pr >> 2;            // batch
    int c0 = (pr & 3) << 2;      // first of 4 channels
    int tid = threadIdx.x;

    extern __shared__ float sm[];
    float* Ar = sm;
    float* Ai = Ar + WBUF;
    float* Br = Ai + WBUF;
    float* Bi = Br + WBUF;
    float2* stag = (float2*)(sm + 4 * WBUF);   // stag[tp*2 + pair]
    unsigned sbase = smem_u32(stag);

    float2 zf0[8], zf1[8];
    float2 keep0[4], keep1[4];

    const float2* xr0 = (const float2*)(x + (size_t)b * TLEN * CCH + c0);
    const float2* xr1 = xr0 + 1;

    // ---------------- forward phase ----------------
    s1_fwd(xr0, Ar, Ai, tid);                       __syncthreads(); // F1
    stage_mid<false, 8 >(Ar, Ai, Br, Bi, tid);      __syncthreads(); // F2
    stage_mid<false, 64>(Br, Bi, Ar, Ai, tid);      __syncthreads(); // F3
    // F4: s4(fwd p0) -> zf0  ||  s1(fwd p1) -> B
    s4_read<false>(Ar, Ai, zf0, tid);
    s1_fwd(xr1, Br, Bi, tid);                       __syncthreads();
    stage_mid<false, 8 >(Br, Bi, Ar, Ai, tid);      __syncthreads(); // F5
    stage_mid<false, 64>(Ar, Ai, Br, Bi, tid);      __syncthreads(); // F6
    // F7: s4(fwd p1) -> zf1  ||  s1(mode0 p0) -> A
    s4_read<false>(Br, Bi, zf1, tid);
    s1_from_zf(zf0, d_ccx[0], Ar, Ai, tid);         __syncthreads();
    stage_mid<true, 8 >(Ar, Ai, Br, Bi, tid);       __syncthreads(); // s2 m0p0
    stage_mid<true, 64>(Br, Bi, Ar, Ai, tid);       __syncthreads(); // s3 m0p0

    // ---------------- mode loop ----------------
    #pragma unroll 1
    for (int k = 0; k < KM; k++) {
        int bk = b * KM + k;
        // P1a: s1(p1,k) -> B ; tid0: issue+commit+drain H2(k-1)
        if (use_tma && tid == 0 && k > 0) {
            #pragma unroll
            for (int j = 0; j < 8; j++)
                tma_st3d(&tmap, c0, 2048 + j * 256, bk - 1, sbase + j * 4096);
            tma_commit();
        }
        s1_from_zf(zf1, d_ccx[k], Br, Bi, tid);
        if (use_tma && tid == 0 && k > 0) tma_wait0();
        __syncthreads();
        // P1b: s4(p0,k) reads A -> stage H1 ch01 + keep0 (or direct store)
        {
            float2 y[8];
            s4_read<true>(Ar, Ai, y, tid);
            if (use_tma) {
                #pragma unroll
                for (int r = 0; r < 4; r++) {
                    stag[(tid + 512 * r) * 2 + 0] = y[r];
                    keep0[r] = y[r + 4];
                }
            } else {
                float2* orow = (float2*)(out + ((size_t)bk * TLEN) * CCH + c0);
                #pragma unroll
                for (int r = 0; r < 8; r++)
                    orow[(tid + 512 * r) * (CCH / 2)] = y[r];
            }
        }
        __syncthreads();
        stage_mid<true, 8 >(Br, Bi, Ar, Ai, tid);   __syncthreads(); // P2 s2 p1
        stage_mid<true, 64>(Ar, Ai, Br, Bi, tid);   __syncthreads(); // P3 s3 p1
        // P4: s4(p1,k) reads B -> stage H1 ch23 + keep1 || s1(p0,k+1) -> A
        {
            float2 y[8];
            s4_read<true>(Br, Bi, y, tid);
            if (use_tma) {
                #pragma unroll
                for (int r = 0; r < 4; r++) {
                    stag[(tid + 512 * r) * 2 + 1] = y[r];
                    keep1[r] = y[r + 4];
                }
            } else {
                float2* orow = (float2*)(out + ((size_t)bk * TLEN) * CCH
                                         + c0 + 2);
                #pragma unroll
                for (int r = 0; r < 8; r++)
                    orow[(tid + 512 * r) * (CCH / 2)] = y[r];
            }
            if (k < KM - 1)
                s1_from_zf(zf0, d_ccx[k + 1], Ar, Ai, tid);
        }
        if (use_tma) fence_async_smem();
        __syncthreads();
        // P5: tid0 issue+commit H1(k) ; s2(p0,k+1) A->B ; tid0 drain H1(k)
        if (use_tma && tid == 0) {
            #pragma unroll
            for (int j = 0; j < 8; j++)
                tma_st3d(&tmap, c0, j * 256, bk, sbase + j * 4096);
            tma_commit();
        }
        if (k < KM - 1) stage_mid<true, 8 >(Ar, Ai, Br, Bi, tid);
        if (use_tma && tid == 0) tma_wait0();
        __syncthreads();
        // P6: s3(p0,k+1) B->A ; write H2(k) from keep regs
        if (k < KM - 1) stage_mid<true, 64>(Br, Bi, Ar, Ai, tid);
        if (use_tma) {
            #pragma unroll
            for (int r = 0; r < 4; r++) {
                stag[(tid + 512 * r) * 2 + 0] = keep0[r];
                stag[(tid + 512 * r) * 2 + 1] = keep1[r];
            }
            fence_async_smem();
        }
        __syncthreads();
    }
    // epilogue: flush H2(7)
    if (use_tma && tid == 0) {
        #pragma unroll
        for (int j = 0; j < 8; j++)
            tma_st3d(&tmap, c0, 2048 + j * 256, b * KM + 7, sbase + j * 4096);
        tma_commit();
        tma_wait0();
    }
    __syncthreads();
}

// ------------------------------ launch -------------------------------------
typedef CUresult (*EncodeTiledFn)(
    CUtensorMap*, CUtensorMapDataType, cuuint32_t, void*,
    const cuuint64_t*, const cuuint64_t*, const cuuint32_t*, const cuuint32_t*,
    CUtensorMapInterleave, CUtensorMapSwizzle, CUtensorMapL2promotion,
    CUtensorMapFloatOOBfill);

extern "C" void kernel_launch(void* const* d_in, const int* in_sizes, int n_in,
                              void* d_out, int out_size) {
    const float* x  = (const float*)d_in[0];
    const float* la = (const float*)d_in[1];
    const float* rt = (const float*)d_in[2];
    const float* rw = (const float*)d_in[3];
    float* out = (float*)d_out;

    // TMA descriptor for out viewed as (C=16, T=4096, B*K=512) f32.
    CUtensorMap tmap;
    memset(&tmap, 0, sizeof(tmap));
    int use_tma = 0;
    void* sym = nullptr;
    cudaDriverEntryPointQueryResult qr = cudaDriverEntryPointSymbolNotFound;
    cudaError_t qe = cudaGetDriverEntryPointByVersion(
        "cuTensorMapEncodeTiled", &sym, 12000, cudaEnableDefault, &qr);
    if (qe == cudaSuccess && sym && qr == cudaDriverEntryPointSuccess) {
        cuuint64_t dims[3]    = {16, 4096, 512};
        cuuint64_t strides[2] = {16 * 4, (cuuint64_t)4096 * 16 * 4};
        cuuint32_t box[3]     = {4, 256, 1};
        cuuint32_t estr[3]    = {1, 1, 1};
        EncodeTiledFn enc = (EncodeTiledFn)sym;
        CUresult r = enc(&tmap, CU_TENSOR_MAP_DATA_TYPE_FLOAT32, 3, out,
                         dims, strides, box, estr,
                         CU_TENSOR_MAP_INTERLEAVE_NONE,
                         CU_TENSOR_MAP_SWIZZLE_NONE,
                         CU_TENSOR_MAP_L2_PROMOTION_L2_128B,
                         CU_TENSOR_MAP_FLOAT_OOB_FILL_NONE);
        use_tma = (r == CUDA_SUCCESS) ? 1 : 0;
    }

    cudaFuncSetAttribute(uvmd_main, cudaFuncAttributeMaxDynamicSharedMemorySize,
                         SMEM_BYTES);

    uvmd_init<<<65, 32>>>(la, rt, rw);
    uvmd_main<<<64 * 4, NTH, SMEM_BYTES>>>(x, out, tmap, use_tma);
}